// round 13
// baseline (speedup 1.0000x reference)
#include <cuda_runtime.h>

#define B_   32
#define IN_  2048
#define DK   8      // Din
#define N_   64     // num output capsules
#define C_   32     // weight channels
#define DD   16     // Dout
#define IPC  (IN_/C_)   // 64 input capsules per channel
#define GRID 1024
#define TPB  128

typedef unsigned long long u64;

// scratch (device globals — no allocation allowed), 16B-aligned for vector ops
__device__ __align__(16) float g_X[B_*C_*DK];    // per-channel x sums (iter 0)
__device__ __align__(16) float g_U[B_*N_*C_*DK]; // accumulated out^T W (logits via U.x)
__device__ __align__(16) float g_y[B_*N_*C_*DK]; // coef-weighted x sums

// ---------------------------------------------------------------------------
// packed f32x2 helpers (sm_103a: FFMA2/FADD2 only reachable via PTX)
// ---------------------------------------------------------------------------
__device__ __forceinline__ u64 fma2(u64 a, u64 b, u64 c) {
    u64 d; asm("fma.rn.f32x2 %0, %1, %2, %3;" : "=l"(d) : "l"(a), "l"(b), "l"(c)); return d;
}
__device__ __forceinline__ u64 mul2(u64 a, u64 b) {
    u64 d; asm("mul.rn.f32x2 %0, %1, %2;" : "=l"(d) : "l"(a), "l"(b)); return d;
}
__device__ __forceinline__ u64 add2(u64 a, u64 b) {
    u64 d; asm("add.rn.f32x2 %0, %1, %2;" : "=l"(d) : "l"(a), "l"(b)); return d;
}
__device__ __forceinline__ u64 pack2(float lo, float hi) {
    u64 d; asm("mov.b64 %0, {%1, %2};" : "=l"(d) : "f"(lo), "f"(hi)); return d;
}
__device__ __forceinline__ float2 unpack2(u64 v) {
    float lo, hi; asm("mov.b64 {%0, %1}, %2;" : "=f"(lo), "=f"(hi) : "l"(v));
    return make_float2(lo, hi);
}
__device__ __forceinline__ ulonglong2 ldcg2(const void* p) {
    ulonglong2 v;
    asm volatile("ld.global.cg.v2.u64 {%0, %1}, [%2];" : "=l"(v.x), "=l"(v.y) : "l"(p));
    return v;
}

// ---------------------------------------------------------------------------
// Per-b barrier: 32 independent pipelines, 32 CTA arrivals each, monotonic
// counters (no resets -> deterministic across graph replays). acq/rel atomics
// instead of full MEMBAR.GPU. Padded 256B apart -> distinct L2 slices.
// ---------------------------------------------------------------------------
__device__ unsigned b_cnt[B_*64];
__device__ unsigned b_gen[B_*64];

__device__ __forceinline__ unsigned atom_add_rel(unsigned* p, unsigned v) {
    unsigned old;
    asm volatile("atom.add.release.gpu.u32 %0, [%1], %2;" : "=r"(old) : "l"(p), "r"(v) : "memory");
    return old;
}
__device__ __forceinline__ unsigned ld_acq(const unsigned* p) {
    unsigned v;
    asm volatile("ld.acquire.gpu.u32 %0, [%1];" : "=r"(v) : "l"(p) : "memory");
    return v;
}
__device__ __forceinline__ void st_rel(unsigned* p, unsigned v) {
    asm volatile("st.release.gpu.u32 [%0], %1;" :: "l"(p), "r"(v) : "memory");
}

__device__ __forceinline__ void b_sync(int b) {
    __syncthreads();
    if (threadIdx.x == 0) {
        unsigned* gp = &b_gen[b*64];
        unsigned gen = ld_acq(gp);                  // MUST read before arriving
        // release-arrive publishes this CTA's prior writes
        if ((atom_add_rel(&b_cnt[b*64], 1u) & 31u) == 31u) {
            st_rel(gp, gen + 1u);                   // release this b-group
        } else {
            while (ld_acq(gp) == gen) __nanosleep(20);
        }
    }
    __syncthreads();
}

// ---------------------------------------------------------------------------
// ks phase: CTA handles (b, n=2m + w>>1); 2 warps per n split the c-loop 16/16.
//   s[d] = sum_{c,k} W[n,c,d,k]*yv[b,n,c,k] (+scale) + bias[n,d]; out=squash(s)
//   MODE 0: yv = X (n-independent), scale 1/64, U  = out^T W (overwrite)
//   MODE 1: yv = g_y, U += out^T W
//   MODE 2: yv = g_y, write final output, skip U
// lane l: d = l>>1, k-quad = l&1 (ulonglong2 #l of the 32-unit W[n][c] block).
// ---------------------------------------------------------------------------
template<int MODE>
__device__ __forceinline__ void ks_phase(const float* __restrict__ W,
                                         const float* __restrict__ bias,
                                         float* __restrict__ out,
                                         float* sbuf, int b, int m) {
    int t = threadIdx.x;
    int w = t >> 5, l = t & 31;
    int h = w & 1;                        // c-half: [h*16, h*16+16)
    int n = m*2 + (w >> 1);               // warps {0,1}->n=2m, {2,3}->n=2m+1

    // ---- s partial over this warp's 16 channels (packed f32x2)
    const ulonglong2* Wc2 = (const ulonglong2*)(W + (size_t)n * C_ * DD * DK) + l;
    u64 acc2 = 0ull;                      // two packed +0.0f
    if (MODE == 0) {
        const ulonglong2* yp2 = (const ulonglong2*)(g_X + b*C_*DK) + (l & 1);
        #pragma unroll 8
        for (int cc = 0; cc < 16; ++cc) {
            int c = h*16 + cc;
            ulonglong2 wv = Wc2[c*32];
            ulonglong2 yv = yp2[c*2];
            acc2 = fma2(wv.x, yv.x, acc2);
            acc2 = fma2(wv.y, yv.y, acc2);
        }
    } else {
        const ulonglong2* yp2 = (const ulonglong2*)(g_y + (size_t)((b*N_ + n)*C_)*DK) + (l & 1);
        #pragma unroll 8
        for (int cc = 0; cc < 16; ++cc) {
            int c = h*16 + cc;
            ulonglong2 wv = Wc2[c*32];
            ulonglong2 yv = ldcg2(yp2 + c*2);   // written by other CTAs of this b-group
            acc2 = fma2(wv.x, yv.x, acc2);
            acc2 = fma2(wv.y, yv.y, acc2);
        }
    }
    float2 af = unpack2(acc2);
    float acc = af.x + af.y;
    if (MODE == 0) acc *= (1.f/64.f);
    acc += __shfl_xor_sync(0xffffffffu, acc, 1);   // combine two k-quads per d

    // cross-warp combine of the two c-halves through smem
    sbuf[w*32 + l] = acc;
    __syncthreads();
    float s = acc + sbuf[(w^1)*32 + l] + bias[n*DD + (l >> 1)];

    // squash (redundant in both warps of the pair — avoids a second sync)
    float sq = s * s;
    #pragma unroll
    for (int off = 2; off < 32; off <<= 1) sq += __shfl_xor_sync(0xffffffffu, sq, off);
    float scale = sq / (1.f + sq) * rsqrtf(sq + 1e-7f);
    float o = scale * s;                  // out_d on lanes 2d, 2d+1

    if (MODE == 2) {
        if (h == 0 && (l & 1) == 0) out[(size_t)(b*N_ + n)*DD + (l>>1)] = o;
        return;
    }

    // ---- U partial: U[b,n,c,k] (+)= sum_d o_d * W[n,c,d,k] for this c-half
    int g = l >> 3;
    float o0 = __shfl_sync(0xffffffffu, o, (g     ) * 2);
    float o1 = __shfl_sync(0xffffffffu, o, (g +  4) * 2);
    float o2 = __shfl_sync(0xffffffffu, o, (g +  8) * 2);
    float o3 = __shfl_sync(0xffffffffu, o, (g + 12) * 2);

    const float* Ws = W + (size_t)n * C_ * DD * DK + l;
    float* Up = g_U + (size_t)((b*N_ + n)*C_) * DK;
    #pragma unroll 8
    for (int cc = 0; cc < 16; ++cc) {
        int c = h*16 + cc;
        const float* wc = Ws + c * DD * DK;
        float u = o0*wc[0] + o1*wc[32] + o2*wc[64] + o3*wc[96];
        u += __shfl_xor_sync(0xffffffffu, u, 8);
        u += __shfl_xor_sync(0xffffffffu, u, 16);
        if (l < 8) {
            if (MODE == 0) Up[c*DK + l] = u;
            else           Up[c*DK + l] = u + __ldcg(Up + c*DK + l);
        }
    }
}

// ---------------------------------------------------------------------------
// route phase: CTA = channel (b, c=m). 4 warps x 16 capsules each.
// lane l handles n0=l, n1=l+32: logits = U.x (packed f32x2 over k-pairs),
// softmax over 64 n (warp butterfly), packed register-resident partial y,
// 4-way packed combine through smem. x tile staged once (route1), reused.
// ---------------------------------------------------------------------------
__device__ __forceinline__ void route_phase(const float* __restrict__ x,
                                            float* xs, float* ybuf,
                                            int b, int c, bool stage) {
    int t = threadIdx.x;
    float4* xs4 = (float4*)xs;

    if (stage) {
        const float4* xg = (const float4*)(x + (size_t)(b*IN_ + c*IPC) * DK);
        xs4[t] = xg[t];                  // 128 float4 = 512 floats
    }
    __syncthreads();

    int w = t >> 5, l = t & 31;

    // U rows for n0=l, n1=l+32 as packed k-pairs (other-CTA writes -> ldcg)
    const char* Ubase = (const char*)g_U + ((size_t)(b*N_)*C_ + c) * (DK*4);
    ulonglong2 U0a = ldcg2(Ubase + (size_t)l*(C_*DK*4));
    ulonglong2 U0b = ldcg2(Ubase + (size_t)l*(C_*DK*4) + 16);
    ulonglong2 U1a = ldcg2(Ubase + (size_t)(l+32)*(C_*DK*4));
    ulonglong2 U1b = ldcg2(Ubase + (size_t)(l+32)*(C_*DK*4) + 16);
    u64 u00 = U0a.x, u01 = U0a.y, u02 = U0b.x, u03 = U0b.y;
    u64 u10 = U1a.x, u11 = U1a.y, u12 = U1b.x, u13 = U1b.y;

    u64 y00 = 0, y01 = 0, y02 = 0, y03 = 0;   // n0: packed k-pairs
    u64 y10 = 0, y11 = 0, y12 = 0, y13 = 0;   // n1

    const ulonglong2* xw2 = (const ulonglong2*)xs + w*32;   // 16 capsules x 2
    #pragma unroll 4
    for (int i = 0; i < 16; ++i) {
        ulonglong2 xa = xw2[i*2], xb = xw2[i*2 + 1];
        u64 a0 = fma2(u00, xa.x, fma2(u01, xa.y, fma2(u02, xb.x, mul2(u03, xb.y))));
        u64 a1 = fma2(u10, xa.x, fma2(u11, xa.y, fma2(u12, xb.x, mul2(u13, xb.y))));
        float2 f0 = unpack2(a0), f1 = unpack2(a1);
        float l0 = f0.x + f0.y, l1 = f1.x + f1.y;
        float e0 = __expf(l0), e1 = __expf(l1);   // |logit| small: no max-sub
        float ts = e0 + e1;
        #pragma unroll
        for (int off = 1; off < 32; off <<= 1) ts += __shfl_xor_sync(0xffffffffu, ts, off);
        float inv = __fdividef(1.f, ts);
        u64 c0p = pack2(e0*inv, e0*inv);
        u64 c1p = pack2(e1*inv, e1*inv);
        y00 = fma2(c0p, xa.x, y00); y01 = fma2(c0p, xa.y, y01);
        y02 = fma2(c0p, xb.x, y02); y03 = fma2(c0p, xb.y, y03);
        y10 = fma2(c1p, xa.x, y10); y11 = fma2(c1p, xa.y, y11);
        y12 = fma2(c1p, xb.x, y12); y13 = fma2(c1p, xb.y, y13);
    }

    // per-warp partials -> smem (each warp: 64 n x 2 ulonglong2 = 128 slots)
    ulonglong2* yb2 = (ulonglong2*)ybuf + w * 128;
    yb2[l*2]          = make_ulonglong2(y00, y01);
    yb2[l*2 + 1]      = make_ulonglong2(y02, y03);
    yb2[(l+32)*2]     = make_ulonglong2(y10, y11);
    yb2[(l+32)*2 + 1] = make_ulonglong2(y12, y13);
    __syncthreads();

    // 4-way packed combine: thread t owns slot t = (n = t>>1, half = t&1)
    ulonglong2* yb = (ulonglong2*)ybuf;
    ulonglong2 p0 = yb[t], p1 = yb[t+128], p2 = yb[t+256], p3 = yb[t+384];
    u64 rx = add2(add2(p0.x, p1.x), add2(p2.x, p3.x));
    u64 ry = add2(add2(p0.y, p1.y), add2(p2.y, p3.y));
    int n = t >> 1, hf = t & 1;
    ((ulonglong2*)g_y)[((size_t)(b*N_ + n)*C_ + c)*2 + hf] = make_ulonglong2(rx, ry);
}

// ---------------------------------------------------------------------------
// One fused persistent kernel: grid 1024 x 128 = 32 independent b-pipelines
// of 32 CTAs each. Single wave: __launch_bounds__(128,8) -> regs<=64 ->
// 8 CTAs/SM -> capacity 1184 >= 1024. smem 10KB/CTA.
// ---------------------------------------------------------------------------
__global__ void __launch_bounds__(TPB, 8) fused_kernel(
        const float* __restrict__ x, const float* __restrict__ W,
        const float* __restrict__ bias, float* __restrict__ out) {
    __shared__ __align__(16) float xs[IPC*DK];    // 2KB: channel x tile
    __shared__ __align__(16) float ybuf[4*N_*DK]; // 8KB: partial-y combine / ks sbuf

    int b = blockIdx.x >> 5;            // pipeline id (batch index)
    int m = blockIdx.x & 31;            // CTA index within pipeline

    // Phase 1: X[b,c,k] = sum_{j<64} x[b, c*64+j, k]
    // CTA m computes 8 outputs ck = m*8..m*8+7: 16 lanes/output, 4 loads/lane.
    {
        int w = threadIdx.x >> 5, l = threadIdx.x & 31;
        int ck = m*8 + w*2 + (l >> 4);
        int c = ck >> 3, k = ck & 7;
        int sub = l & 15;
        const float* xp = x + (size_t)b*IN_*DK + (size_t)c*IPC*DK + sub*4*DK + k;
        float s = xp[0] + xp[DK] + xp[2*DK] + xp[3*DK];
        s += __shfl_xor_sync(0xffffffffu, s, 1);
        s += __shfl_xor_sync(0xffffffffu, s, 2);
        s += __shfl_xor_sync(0xffffffffu, s, 4);
        s += __shfl_xor_sync(0xffffffffu, s, 8);
        if (sub == 0) g_X[b*C_*DK + ck] = s;
    }
    b_sync(b);
    ks_phase<0>(W, bias, out, ybuf, b, m);   // iter 0: uniform coef, build U
    b_sync(b);
    route_phase(x, xs, ybuf, b, m, true);    // iter 1: softmax(U.x) -> y
    b_sync(b);
    ks_phase<1>(W, bias, out, ybuf, b, m);   // iter 1: s,out, U += ...
    b_sync(b);
    route_phase(x, xs, ybuf, b, m, false);   // iter 2 (x tile already in smem)
    b_sync(b);
    ks_phase<2>(W, bias, out, ybuf, b, m);   // iter 2: final output
}

// ---------------------------------------------------------------------------
extern "C" void kernel_launch(void* const* d_in, const int* in_sizes, int n_in,
                              void* d_out, int out_size) {
    const float* x    = (const float*)d_in[0];   // [32, 2048, 8]
    const float* W    = (const float*)d_in[1];   // [64, 32, 16, 8]
    const float* bias = (const float*)d_in[2];   // [64, 16]
    float* out = (float*)d_out;                  // [32, 64, 16]

    fused_kernel<<<GRID, TPB>>>(x, W, bias, out);
}

// round 15
// speedup vs baseline: 1.1059x; 1.1059x over previous
#include <cuda_runtime.h>

#define B_   32
#define IN_  2048
#define DK   8      // Din
#define N_   64     // num output capsules
#define C_   32     // weight channels
#define DD   16     // Dout
#define IPC  (IN_/C_)   // 64 input capsules per channel
#define QB   8      // CTAs per batch pipeline
#define GRID (B_*QB)   // 256
#define TPB  256

typedef unsigned long long u64;

// scratch (device globals — no allocation allowed), 16B-aligned for vector ops
__device__ __align__(16) float g_X[B_*C_*DK];    // per-channel x sums (iter 0)
__device__ __align__(16) float g_U[B_*N_*C_*DK]; // accumulated out^T W (logits via U.x)
__device__ __align__(16) float g_y[B_*N_*C_*DK]; // coef-weighted x sums

// ---------------------------------------------------------------------------
// packed f32x2 helpers (sm_103a: FFMA2/FADD2 only reachable via PTX)
// ---------------------------------------------------------------------------
__device__ __forceinline__ u64 fma2(u64 a, u64 b, u64 c) {
    u64 d; asm("fma.rn.f32x2 %0, %1, %2, %3;" : "=l"(d) : "l"(a), "l"(b), "l"(c)); return d;
}
__device__ __forceinline__ u64 mul2(u64 a, u64 b) {
    u64 d; asm("mul.rn.f32x2 %0, %1, %2;" : "=l"(d) : "l"(a), "l"(b)); return d;
}
__device__ __forceinline__ u64 add2(u64 a, u64 b) {
    u64 d; asm("add.rn.f32x2 %0, %1, %2;" : "=l"(d) : "l"(a), "l"(b)); return d;
}
__device__ __forceinline__ u64 pack2(float lo, float hi) {
    u64 d; asm("mov.b64 %0, {%1, %2};" : "=l"(d) : "f"(lo), "f"(hi)); return d;
}
__device__ __forceinline__ float2 unpack2(u64 v) {
    float lo, hi; asm("mov.b64 {%0, %1}, %2;" : "=f"(lo), "=f"(hi) : "l"(v));
    return make_float2(lo, hi);
}
__device__ __forceinline__ ulonglong2 ldcg2(const void* p) {
    ulonglong2 v;
    asm volatile("ld.global.cg.v2.u64 {%0, %1}, [%2];" : "=l"(v.x), "=l"(v.y) : "l"(p));
    return v;
}

// ---------------------------------------------------------------------------
// Per-b barrier: 32 independent pipelines, EIGHT CTA arrivals each, monotonic
// counters (no resets -> deterministic across graph replays). acq_rel arrival
// (transitively carries every arriving CTA's writes into the releaser's
// release-store). Padded 256B apart -> distinct L2 slices.
// ---------------------------------------------------------------------------
__device__ unsigned b_cnt[B_*64];
__device__ unsigned b_gen[B_*64];

__device__ __forceinline__ unsigned atom_add_ar(unsigned* p, unsigned v) {
    unsigned old;
    asm volatile("atom.add.acq_rel.gpu.u32 %0, [%1], %2;" : "=r"(old) : "l"(p), "r"(v) : "memory");
    return old;
}
__device__ __forceinline__ unsigned ld_acq(const unsigned* p) {
    unsigned v;
    asm volatile("ld.acquire.gpu.u32 %0, [%1];" : "=r"(v) : "l"(p) : "memory");
    return v;
}
__device__ __forceinline__ void st_rel(unsigned* p, unsigned v) {
    asm volatile("st.release.gpu.u32 [%0], %1;" :: "l"(p), "r"(v) : "memory");
}

__device__ __forceinline__ void b_sync(int b) {
    __syncthreads();
    if (threadIdx.x == 0) {
        unsigned* gp = &b_gen[b*64];
        unsigned gen = ld_acq(gp);                   // read BEFORE arriving
        if ((atom_add_ar(&b_cnt[b*64], 1u) & (QB-1u)) == QB-1u) {
            st_rel(gp, gen + 1u);                    // release this b-group
        } else {
            while (ld_acq(gp) == gen) __nanosleep(20);
        }
    }
    __syncthreads();
}

// ---------------------------------------------------------------------------
// ks phase: warp w (0..7) owns n = q*8 + w, FULL 32-channel loop (no cross-
// warp combine, no syncthreads).
//   s[d] = sum_{c,k} W[n,c,d,k]*yv[b,n,c,k] (+scale) + bias[n,d]; out=squash(s)
//   MODE 0: yv = X (n-independent), scale 1/64, U  = out^T W (overwrite)
//   MODE 1: yv = g_y, U += out^T W
//   MODE 2: yv = g_y, write final output, skip U
// lane l: d = l>>1, k-quad = l&1 (ulonglong2 #l of the 32-unit W[n][c] block).
// ---------------------------------------------------------------------------
template<int MODE>
__device__ __forceinline__ void ks_phase(const float* __restrict__ W,
                                         const float* __restrict__ bias,
                                         float* __restrict__ out,
                                         int b, int q) {
    int t = threadIdx.x;
    int w = t >> 5, l = t & 31;
    int n = q*8 + w;

    // ---- s over all 32 channels (packed f32x2)
    const ulonglong2* Wc2 = (const ulonglong2*)(W + (size_t)n * C_ * DD * DK) + l;
    u64 acc2 = 0ull;
    if (MODE == 0) {
        const ulonglong2* yp2 = (const ulonglong2*)(g_X + b*C_*DK) + (l & 1);
        #pragma unroll 8
        for (int c = 0; c < C_; ++c) {
            ulonglong2 wv = Wc2[c*32];
            ulonglong2 yv = yp2[c*2];
            acc2 = fma2(wv.x, yv.x, acc2);
            acc2 = fma2(wv.y, yv.y, acc2);
        }
    } else {
        const ulonglong2* yp2 = (const ulonglong2*)(g_y + (size_t)((b*N_ + n)*C_)*DK) + (l & 1);
        #pragma unroll 8
        for (int c = 0; c < C_; ++c) {
            ulonglong2 wv = Wc2[c*32];
            ulonglong2 yv = ldcg2(yp2 + c*2);   // written by other CTAs of this b-group
            acc2 = fma2(wv.x, yv.x, acc2);
            acc2 = fma2(wv.y, yv.y, acc2);
        }
    }
    float2 af = unpack2(acc2);
    float acc = af.x + af.y;
    if (MODE == 0) acc *= (1.f/64.f);
    acc += __shfl_xor_sync(0xffffffffu, acc, 1);   // combine two k-quads per d
    float s = acc + bias[n*DD + (l >> 1)];

    // squash: lanes hold d=l>>1 duplicated; off 2..16 sums the 16 distinct d
    float sq = s * s;
    #pragma unroll
    for (int off = 2; off < 32; off <<= 1) sq += __shfl_xor_sync(0xffffffffu, sq, off);
    float scale = sq / (1.f + sq) * rsqrtf(sq + 1e-7f);
    float o = scale * s;                  // out_d on lanes 2d, 2d+1

    if (MODE == 2) {
        if ((l & 1) == 0) out[(size_t)(b*N_ + n)*DD + (l>>1)] = o;
        return;                           // last phase: no barrier after
    }

    // ---- U: U[b,n,c,k] (+)= sum_d o_d * W[n,c,d,k], all 32 channels
    int g = l >> 3;
    float o0 = __shfl_sync(0xffffffffu, o, (g     ) * 2);
    float o1 = __shfl_sync(0xffffffffu, o, (g +  4) * 2);
    float o2 = __shfl_sync(0xffffffffu, o, (g +  8) * 2);
    float o3 = __shfl_sync(0xffffffffu, o, (g + 12) * 2);

    const float* Ws = W + (size_t)n * C_ * DD * DK + l;
    float* Up = g_U + (size_t)((b*N_ + n)*C_) * DK;
    #pragma unroll 8
    for (int c = 0; c < C_; ++c) {
        const float* wc = Ws + c * DD * DK;
        float u = o0*wc[0] + o1*wc[32] + o2*wc[64] + o3*wc[96];
        u += __shfl_xor_sync(0xffffffffu, u, 8);
        u += __shfl_xor_sync(0xffffffffu, u, 16);
        if (l < 8) {
            if (MODE == 0) Up[c*DK + l] = u;
            else           Up[c*DK + l] = u + __ldcg(Up + c*DK + l); // same warp wrote it
        }
    }
}

// ---------------------------------------------------------------------------
// route phase: CTA owns 4 channels c = q*4 + (w>>1); warp-half hw = w&1 takes
// capsules [hw*32, hw*32+32). lane l handles n0=l, n1=l+32: logits = U.x
// (packed f32x2), softmax over 64 n (warp butterfly), packed partial y,
// 2-warp packed combine through smem. x tile (4 channels) staged once, reused.
// ---------------------------------------------------------------------------
__device__ __forceinline__ void route_phase(const float* __restrict__ x,
                                            float* xs, float* ybuf,
                                            int b, int q, bool stage) {
    int t = threadIdx.x;
    float4* xs4 = (float4*)xs;

    if (stage) {   // 4 channels x 512 floats = 512 float4, 256 threads x 2
        const float4* xg = (const float4*)(x + (size_t)(b*IN_ + q*4*IPC) * DK);
        xs4[t]       = xg[t];
        xs4[t + 256] = xg[t + 256];
    }
    __syncthreads();

    int w = t >> 5, l = t & 31;
    int cl = w >> 1, hw = w & 1;
    int c = q*4 + cl;

    // U rows for n0=l, n1=l+32 as packed k-pairs (other-CTA writes -> ldcg)
    const char* Ubase = (const char*)g_U + ((size_t)(b*N_)*C_ + c) * (DK*4);
    ulonglong2 U0a = ldcg2(Ubase + (size_t)l*(C_*DK*4));
    ulonglong2 U0b = ldcg2(Ubase + (size_t)l*(C_*DK*4) + 16);
    ulonglong2 U1a = ldcg2(Ubase + (size_t)(l+32)*(C_*DK*4));
    ulonglong2 U1b = ldcg2(Ubase + (size_t)(l+32)*(C_*DK*4) + 16);
    u64 u00 = U0a.x, u01 = U0a.y, u02 = U0b.x, u03 = U0b.y;
    u64 u10 = U1a.x, u11 = U1a.y, u12 = U1b.x, u13 = U1b.y;

    u64 y00 = 0, y01 = 0, y02 = 0, y03 = 0;   // n0: packed k-pairs
    u64 y10 = 0, y11 = 0, y12 = 0, y13 = 0;   // n1

    const ulonglong2* xw2 = (const ulonglong2*)xs + (cl*IPC + hw*32)*2;
    #pragma unroll 4
    for (int i = 0; i < 32; ++i) {
        ulonglong2 xa = xw2[i*2], xb = xw2[i*2 + 1];
        u64 a0 = fma2(u00, xa.x, fma2(u01, xa.y, fma2(u02, xb.x, mul2(u03, xb.y))));
        u64 a1 = fma2(u10, xa.x, fma2(u11, xa.y, fma2(u12, xb.x, mul2(u13, xb.y))));
        float2 f0 = unpack2(a0), f1 = unpack2(a1);
        float l0 = f0.x + f0.y, l1 = f1.x + f1.y;
        float e0 = __expf(l0), e1 = __expf(l1);   // |logit| small: no max-sub
        float ts = e0 + e1;
        #pragma unroll
        for (int off = 1; off < 32; off <<= 1) ts += __shfl_xor_sync(0xffffffffu, ts, off);
        float inv = __fdividef(1.f, ts);
        u64 c0p = pack2(e0*inv, e0*inv);
        u64 c1p = pack2(e1*inv, e1*inv);
        y00 = fma2(c0p, xa.x, y00); y01 = fma2(c0p, xa.y, y01);
        y02 = fma2(c0p, xb.x, y02); y03 = fma2(c0p, xb.y, y03);
        y10 = fma2(c1p, xa.x, y10); y11 = fma2(c1p, xa.y, y11);
        y12 = fma2(c1p, xb.x, y12); y13 = fma2(c1p, xb.y, y13);
    }

    // per-warp partials -> smem (each warp: 64 n x 2 ulonglong2 = 128 slots)
    ulonglong2* yb2 = (ulonglong2*)ybuf + w * 128;
    yb2[l*2]          = make_ulonglong2(y00, y01);
    yb2[l*2 + 1]      = make_ulonglong2(y02, y03);
    yb2[(l+32)*2]     = make_ulonglong2(y10, y11);
    yb2[(l+32)*2 + 1] = make_ulonglong2(y12, y13);
    __syncthreads();

    // 2-warp combine: thread t -> channel ch = t>>6, slots s and s+64
    ulonglong2* yb = (ulonglong2*)ybuf;
    int ch = t >> 6, s0 = t & 63;
    int cg = q*4 + ch;
    #pragma unroll
    for (int r = 0; r < 2; ++r) {
        int slot = s0 + r*64;
        ulonglong2 p0 = yb[(ch*2    )*128 + slot];
        ulonglong2 p1 = yb[(ch*2 + 1)*128 + slot];
        u64 rx = add2(p0.x, p1.x);
        u64 ry = add2(p0.y, p1.y);
        int n = slot >> 1, hf = slot & 1;
        ((ulonglong2*)g_y)[((size_t)(b*N_ + n)*C_ + cg)*2 + hf] = make_ulonglong2(rx, ry);
    }
}

// ---------------------------------------------------------------------------
// One fused persistent kernel: grid 256 x 256 = 32 independent b-pipelines of
// EIGHT CTAs each. Single wave: __launch_bounds__(256,2) -> 2 CTAs/SM ->
// capacity 296 >= 256. smem 24KB/CTA -> 48KB/SM at 2 CTAs, fine.
// ---------------------------------------------------------------------------
__global__ void __launch_bounds__(TPB, 2) fused_kernel(
        const float* __restrict__ x, const float* __restrict__ W,
        const float* __restrict__ bias, float* __restrict__ out) {
    __shared__ __align__(16) float xs[4*IPC*DK];    // 8KB: 4-channel x tile
    __shared__ __align__(16) float ybuf[8*N_*DK];   // 16KB: 8-warp partial-y combine

    int b = blockIdx.x >> 3;            // pipeline id (batch index)
    int q = blockIdx.x & (QB-1);        // CTA index within pipeline

    // Phase 1: X[b,c,k] = sum_{j<64} x[b, c*64+j, k]
    // CTA q computes 32 outputs ck = q*32..q*32+31: 8 lanes/output, 8 loads each.
    {
        int t = threadIdx.x, l = t & 31;
        int ck = q*32 + (t >> 3);
        int c = ck >> 3, k = ck & 7;
        int sub = l & 7;
        const float* xp = x + (size_t)b*IN_*DK + (size_t)c*IPC*DK + sub*8*DK + k;
        float s = 0.f;
        #pragma unroll
        for (int j = 0; j < 8; ++j) s += xp[j*DK];
        s += __shfl_xor_sync(0xffffffffu, s, 1);
        s += __shfl_xor_sync(0xffffffffu, s, 2);
        s += __shfl_xor_sync(0xffffffffu, s, 4);
        if (sub == 0) g_X[b*C_*DK + ck] = s;
    }
    b_sync(b);
    ks_phase<0>(W, bias, out, b, q);         // iter 0: uniform coef, build U
    b_sync(b);
    route_phase(x, xs, ybuf, b, q, true);    // iter 1: softmax(U.x) -> y
    b_sync(b);
    ks_phase<1>(W, bias, out, b, q);         // iter 1: s,out, U += ...
    b_sync(b);
    route_phase(x, xs, ybuf, b, q, false);   // iter 2 (x tile already in smem)
    b_sync(b);
    ks_phase<2>(W, bias, out, b, q);         // iter 2: final output
}

// ---------------------------------------------------------------------------
extern "C" void kernel_launch(void* const* d_in, const int* in_sizes, int n_in,
                              void* d_out, int out_size) {
    const float* x    = (const float*)d_in[0];   // [32, 2048, 8]
    const float* W    = (const float*)d_in[1];   // [64, 32, 16, 8]
    const float* bias = (const float*)d_in[2];   // [64, 16]
    float* out = (float*)d_out;                  // [32, 64, 16]

    fused_kernel<<<GRID, TPB>>>(x, W, bias, out);
}